// round 3
// baseline (speedup 1.0000x reference)
#include <cuda_runtime.h>
#include <cstddef>

// Persistent-kernel LSTM:  B=512, S=512, D=128, H=256, 4H=1024.
// R2: 256 threads/CTA (2 warps per SMSP for latency hiding), weights resident
// in shared memory for the whole sequence, gate-packed B layout so the inner
// loop is 2xLDS.128 + 4xMOV + 8xFFMA2 per k per thread.

#define SEQ    512
#define BATCH  512
#define DIM    128
#define HID    256
#define G4     1024
#define NCTA   128
#define NTHR   256
#define KTOT   384
#define KC     32
#define NCHUNK 12            // 384 / 32
#define PITCH  68            // A-tile row pitch (floats), 16B-aligned rows
#define SB_FLOATS (KTOT * 64)          // persistent weight slice: 96 KB
#define SA_FLOATS (KC * PITCH)         // one A buffer: 8.5 KB
#define SMEM_BYTES ((SB_FLOATS + 2 * SA_FLOATS) * 4)

// ---- persistent device scratch (no allocations allowed) ----
__device__ float g_h[2][BATCH * HID];          // double-buffered hidden state
__device__ unsigned long long g_bar = 0;       // monotonic barrier ticket

// ---- packed fp32x2 helpers ----
__device__ __forceinline__ void fma2(unsigned long long &d,
                                     unsigned long long a,
                                     unsigned long long b) {
    asm("fma.rn.f32x2 %0, %1, %2, %0;" : "+l"(d) : "l"(a), "l"(b));
}
__device__ __forceinline__ unsigned long long pack2(float x) {
    unsigned long long r;
    asm("mov.b64 %0, {%1, %1};" : "=l"(r) : "f"(x));
    return r;
}
__device__ __forceinline__ float2 unpack2(unsigned long long v) {
    float2 f;
    asm("mov.b64 {%0, %1}, %2;" : "=f"(f.x), "=f"(f.y) : "l"(v));
    return f;
}

__device__ __forceinline__ float sigf(float x) {
    return __fdividef(1.0f, 1.0f + __expf(-x));
}
__device__ __forceinline__ float tanhf_fast(float x) {
    return 1.0f - __fdividef(2.0f, 1.0f + __expf(2.0f * x));
}

// Monotonic ticket grid barrier: correct across any number of graph replays.
__device__ __forceinline__ void grid_barrier() {
    __syncthreads();
    if (threadIdx.x == 0) {
        __threadfence();                                  // release h writes
        unsigned long long t = atomicAdd(&g_bar, 1ULL) + 1ULL;
        unsigned long long target =
            ((t + (unsigned long long)NCTA - 1ULL) / NCTA) * (unsigned long long)NCTA;
        unsigned long long v;
        do {
            asm volatile("ld.acquire.gpu.u64 %0, [%1];"
                         : "=l"(v) : "l"(&g_bar) : "memory");
        } while (v < target);
    }
    __syncthreads();
}

__global__ void __launch_bounds__(NTHR, 1)
lstm_persistent(const float* __restrict__ x,  const float* __restrict__ Wx,
                const float* __restrict__ Wh, const float* __restrict__ bv,
                const float* __restrict__ Wd, const float* __restrict__ bd,
                float* __restrict__ out)
{
    extern __shared__ __align__(16) float smem[];
    float* sB = smem;                    // [k][jj*4 + gate], 384 x 64
    float* sA = smem + SB_FLOATS;        // 2 buffers of [k][row] (KC x PITCH)

    const int tid = threadIdx.x;
    const int cta = blockIdx.x;
    const int rt  = cta >> 4;            // 0..7   row tile (64 rows)
    const int jt  = cta & 15;            // 0..15  col tile (16 hidden cols)
    const int r0  = rt * 64;
    const int j0  = jt * 16;
    const int jj  = tid & 15;            // hidden-col within tile
    const int rq  = tid >> 4;            // 0..15, 4 rows each
    const int myr0 = r0 + rq * 4;

    // ---- one-time: load this CTA's 64-column weight slice into smem ----
    // layout: sB[k*64 + jj*4 + gate], gates (i,f,g,o) adjacent per column.
    for (int idx = tid; idx < SB_FLOATS; idx += NTHR) {
        int k = idx >> 6, col = idx & 63;
        int g = col & 3, jjl = col >> 2;
        int gcol = g * HID + j0 + jjl;
        sB[idx] = (k < DIM) ? Wx[(size_t)k * G4 + gcol]
                            : Wh[(size_t)(k - DIM) * G4 + gcol];
    }

    // zero h buffer 0 (h0 = 0); every launch, deterministic
    {
        int base = cta * NTHR + tid;
        #pragma unroll
        for (int i = 0; i < 4; ++i)
            g_h[0][base + i * (NCTA * NTHR)] = 0.0f;
    }

    const float bi = bv[0 * HID + j0 + jj];
    const float bf = bv[1 * HID + j0 + jj];
    const float bg = bv[2 * HID + j0 + jj];
    const float bo = bv[3 * HID + j0 + jj];

    float c4[4] = {0.f, 0.f, 0.f, 0.f};  // cell state: 4 rows x 1 col

    // A loader: each thread brings 2 float4 per chunk (rows lrow0 / lrow0+32)
    const int lrow0 = tid >> 3;          // 0..31
    const int lk0   = (tid & 7) << 2;    // 0,4,...,28

    grid_barrier();                       // h0 + sB visible everywhere

    for (int s = 0; s < SEQ; ++s) {
        const float* __restrict__ hprev = g_h[s & 1];
        float* __restrict__ hnext = g_h[(s + 1) & 1];

        unsigned long long acc[4][2];     // [row][gatepair (i,f)/(g,o)]
        #pragma unroll
        for (int r = 0; r < 4; ++r) { acc[r][0] = 0ULL; acc[r][1] = 0ULL; }

        float4 aR0, aR1;
        auto ldg_chunk = [&](int kbase) {
            if (kbase < DIM) {            // x part of K
                const float* p = x + ((size_t)(r0 + lrow0) * SEQ + s) * DIM + kbase + lk0;
                aR0 = *(const float4*)p;
                aR1 = *(const float4*)(p + (size_t)32 * SEQ * DIM);
            } else {                      // h part: bypass L1 (cross-SM coherence)
                int kb = kbase - DIM;
                const float4* p = (const float4*)(hprev + (size_t)(r0 + lrow0) * HID + kb + lk0);
                aR0 = __ldcv(p);
                aR1 = __ldcv((const float4*)((const float*)p + 32 * HID));
            }
        };
        auto sts_chunk = [&](int buf) {
            float* A = sA + buf * SA_FLOATS;
            A[(lk0 + 0) * PITCH + lrow0] = aR0.x;
            A[(lk0 + 1) * PITCH + lrow0] = aR0.y;
            A[(lk0 + 2) * PITCH + lrow0] = aR0.z;
            A[(lk0 + 3) * PITCH + lrow0] = aR0.w;
            A[(lk0 + 0) * PITCH + lrow0 + 32] = aR1.x;
            A[(lk0 + 1) * PITCH + lrow0 + 32] = aR1.y;
            A[(lk0 + 2) * PITCH + lrow0 + 32] = aR1.z;
            A[(lk0 + 3) * PITCH + lrow0 + 32] = aR1.w;
        };

        ldg_chunk(0);
        sts_chunk(0);
        __syncthreads();

        #pragma unroll 1
        for (int ch = 0; ch < NCHUNK; ++ch) {
            if (ch + 1 < NCHUNK) ldg_chunk((ch + 1) * KC);
            const float* Ab = sA + (ch & 1) * SA_FLOATS;
            const float* Bb = sB + ch * (KC * 64);
            #pragma unroll
            for (int kk = 0; kk < KC; ++kk) {
                float4 av = *(const float4*)(Ab + kk * PITCH + rq * 4);
                ulonglong2 bw = *(const ulonglong2*)(Bb + kk * 64 + jj * 4);
                unsigned long long a0 = pack2(av.x), a1 = pack2(av.y);
                unsigned long long a2 = pack2(av.z), a3 = pack2(av.w);
                fma2(acc[0][0], a0, bw.x); fma2(acc[0][1], a0, bw.y);
                fma2(acc[1][0], a1, bw.x); fma2(acc[1][1], a1, bw.y);
                fma2(acc[2][0], a2, bw.x); fma2(acc[2][1], a2, bw.y);
                fma2(acc[3][0], a3, bw.x); fma2(acc[3][1], a3, bw.y);
            }
            if (ch + 1 < NCHUNK) sts_chunk((ch + 1) & 1);
            __syncthreads();
        }

        // gate epilogue (keras order i,f,g,o): c,h update, h -> global
        #pragma unroll
        for (int r = 0; r < 4; ++r) {
            float2 vif = unpack2(acc[r][0]);
            float2 vgo = unpack2(acc[r][1]);
            float iv = sigf(vif.x + bi);
            float fv = sigf(vif.y + bf);
            float gv = tanhf_fast(vgo.x + bg);
            float ov = sigf(vgo.y + bo);
            c4[r] = fv * c4[r] + iv * gv;
            hnext[(size_t)(myr0 + r) * HID + j0 + jj] = ov * tanhf_fast(c4[r]);
        }

        grid_barrier();
    }

    // ---- classifier + softmax on h_final = g_h[0]; one warp per batch row ----
    {
        const int w = tid >> 5, lane = tid & 31;
        if (w < 4) {
            const int row = cta * 4 + w;              // 128 CTAs x 4 warps = 512 rows
            const float* hf = g_h[0];
            float acc10[10];
            #pragma unroll
            for (int c = 0; c < 10; ++c) acc10[c] = 0.f;
            for (int k = lane; k < HID; k += 32) {
                float hv = __ldcv(hf + (size_t)row * HID + k);
                const float* wd = Wd + (size_t)k * 10;
                #pragma unroll
                for (int c = 0; c < 10; ++c) acc10[c] += hv * wd[c];
            }
            #pragma unroll
            for (int off = 16; off > 0; off >>= 1) {
                #pragma unroll
                for (int c = 0; c < 10; ++c)
                    acc10[c] += __shfl_down_sync(0xffffffffu, acc10[c], off);
            }
            if (lane == 0) {
                float m = -3.0e38f;
                #pragma unroll
                for (int c = 0; c < 10; ++c) { acc10[c] += bd[c]; m = fmaxf(m, acc10[c]); }
                float ssum = 0.f;
                #pragma unroll
                for (int c = 0; c < 10; ++c) { acc10[c] = __expf(acc10[c] - m); ssum += acc10[c]; }
                float inv = 1.0f / ssum;
                #pragma unroll
                for (int c = 0; c < 10; ++c)
                    out[(size_t)row * 10 + c] = acc10[c] * inv;
            }
        }
    }
}

extern "C" void kernel_launch(void* const* d_in, const int* in_sizes, int n_in,
                              void* d_out, int out_size) {
    const float* x  = (const float*)d_in[0];
    const float* Wx = (const float*)d_in[1];
    const float* Wh = (const float*)d_in[2];
    const float* b  = (const float*)d_in[3];
    const float* Wd = (const float*)d_in[4];
    const float* bd = (const float*)d_in[5];
    (void)in_sizes; (void)n_in; (void)out_size;
    cudaFuncSetAttribute(lstm_persistent,
                         cudaFuncAttributeMaxDynamicSharedMemorySize, SMEM_BYTES);
    lstm_persistent<<<NCTA, NTHR, SMEM_BYTES>>>(x, Wx, Wh, b, Wd, bd, (float*)d_out);
}

// round 6
// speedup vs baseline: 2.6727x; 2.6727x over previous
#include <cuda_runtime.h>
#include <cuda_fp16.h>
#include <cstdint>
#include <cstddef>

// R6: persistent LSTM on baseline-ISA tensor cores (mma.sync m16n8k16 fp16,
// fp32 accum) -- tcgen05 is rejected by this harness's compute_103 PTX pass.
// 128 CTAs = 8 M-tiles(64 rows) x 16 N-tiles(64 cols = 16 jl x 4 gates).
// Weights resident in REGISTERS (96 b32/thread, loaded once). A=[x_t|h] fp16
// in 48KB smem, XOR-swizzled for conflict-free ldmatrix. c-state in regs,
// h double-buffered fp16 in global, monotonic ticket grid barrier per step.

#define SEQ   512
#define BATCH 512
#define DIM   128
#define HID   256
#define G4    1024
#define NCTA  128
#define NTHR  256
#define NKS   24             // K = 384 = 24 x 16

// ---- persistent device scratch ----
__device__ __align__(16) __half g_h16[2][BATCH * HID];
__device__ unsigned long long g_bar = 0;

__device__ __forceinline__ uint32_t smem_u32(const void* p) {
    uint32_t a;
    asm("{ .reg .u64 t; cvta.to.shared.u64 t, %1; cvt.u32.u64 %0, t; }"
        : "=r"(a) : "l"(p));
    return a;
}
__device__ __forceinline__ void ldsm4(uint32_t a[4], uint32_t addr) {
    asm volatile("ldmatrix.sync.aligned.m8n8.x4.shared.b16 {%0,%1,%2,%3}, [%4];"
                 : "=r"(a[0]), "=r"(a[1]), "=r"(a[2]), "=r"(a[3]) : "r"(addr));
}
__device__ __forceinline__ void mma16816(float c[4], const uint32_t a[4],
                                         uint32_t b0, uint32_t b1) {
    asm volatile(
        "mma.sync.aligned.m16n8k16.row.col.f32.f16.f16.f32 "
        "{%0,%1,%2,%3}, {%4,%5,%6,%7}, {%8,%9}, {%0,%1,%2,%3};"
        : "+f"(c[0]), "+f"(c[1]), "+f"(c[2]), "+f"(c[3])
        : "r"(a[0]), "r"(a[1]), "r"(a[2]), "r"(a[3]), "r"(b0), "r"(b1));
}

__device__ __forceinline__ float sigf(float x) {
    return __fdividef(1.0f, 1.0f + __expf(-x));
}
__device__ __forceinline__ float tanhf_fast(float x) {
    return 1.0f - __fdividef(2.0f, 1.0f + __expf(2.0f * x));
}

// A-tile swizzled offset: block per kstep = 64 rows x 32B.
__device__ __forceinline__ uint32_t a_phys(int ks, int row, int kh /*0,1*/) {
    return (uint32_t)(ks * 2048 + row * 32 + ((kh << 4) ^ ((row & 4) << 2)));
}

// Monotonic ticket grid barrier (graph-replay-safe).
__device__ __forceinline__ void grid_barrier() {
    __syncthreads();
    if (threadIdx.x == 0) {
        __threadfence();
        unsigned long long t = atomicAdd(&g_bar, 1ULL) + 1ULL;
        unsigned long long target =
            ((t + (unsigned long long)NCTA - 1ULL) / NCTA) * (unsigned long long)NCTA;
        unsigned long long v;
        do {
            asm volatile("ld.acquire.gpu.u64 %0, [%1];" : "=l"(v) : "l"(&g_bar) : "memory");
        } while (v < target);
    }
    __syncthreads();
}

__global__ void __launch_bounds__(NTHR, 1)
lstm_hmma(const float* __restrict__ x,  const float* __restrict__ Wx,
          const float* __restrict__ Wh, const float* __restrict__ bv,
          const float* __restrict__ Wd, const float* __restrict__ bd,
          float* __restrict__ out)
{
    __shared__ __align__(1024) char sA[NKS * 2048];   // 48 KB: [x_t | h] fp16
    const uint32_t sA_u = smem_u32(sA);

    const int tid  = threadIdx.x;
    const int cta  = blockIdx.x;
    const int warp = tid >> 5, lane = tid & 31;
    const int r0 = (cta >> 4) * 64;     // M tile: 64 batch rows
    const int j0 = (cta & 15) * 16;     // 16 hidden cols
    const int wM = warp & 1;            // 2-way M split (32 rows)
    const int wN = warp >> 1;           // 4-way N split (16 n-cols)

    // ---- one-time: B fragments into registers ----
    // n (0..63) = jl*4 + gate ; warp covers n in [wN*16, wN*16+16)
    // b frag (k16n8, col): b0 = (k0,k0+1), b1 = (k0+8,k0+9), n = nbase + lane/4
    uint32_t bfr[NKS][2][2];
    {
        #pragma unroll
        for (int ks = 0; ks < NKS; ++ks) {
            #pragma unroll
            for (int nb = 0; nb < 2; ++nb) {
                int n = wN * 16 + nb * 8 + (lane >> 2);
                int col = (n & 3) * HID + j0 + (n >> 2);
                int k0 = ks * 16 + (lane & 3) * 2;
                float w0, w1, w2, w3;
                if (k0 < DIM) {
                    w0 = Wx[(size_t)k0 * G4 + col];
                    w1 = Wx[(size_t)(k0 + 1) * G4 + col];
                } else {
                    w0 = Wh[(size_t)(k0 - DIM) * G4 + col];
                    w1 = Wh[(size_t)(k0 - DIM + 1) * G4 + col];
                }
                int k8 = k0 + 8;
                if (k8 < DIM) {
                    w2 = Wx[(size_t)k8 * G4 + col];
                    w3 = Wx[(size_t)(k8 + 1) * G4 + col];
                } else {
                    w2 = Wh[(size_t)(k8 - DIM) * G4 + col];
                    w3 = Wh[(size_t)(k8 - DIM + 1) * G4 + col];
                }
                union { __half2 h; uint32_t u; } p0, p1;
                p0.h = __floats2half2_rn(w0, w1);
                p1.h = __floats2half2_rn(w2, w3);
                bfr[ks][nb][0] = p0.u;
                bfr[ks][nb][1] = p1.u;
            }
        }
    }

    // zero h buffer 0
    ((uint2*)g_h16[0])[cta * NTHR + tid] = make_uint2(0u, 0u);

    // epilogue geometry: pair (lane, lane^1) shares jl; even=mb0 rows, odd=mb1
    const int myOdd = lane & 1;
    const int rA = wM * 32 + myOdd * 16 + (lane >> 2);   // rows rA, rA+8
    const int jA = (lane & 3) >> 1;
    // biases per nb (jcol = j0 + wN*4 + nb*2 + jA)
    float bI[2], bF[2], bG[2], bO[2];
    #pragma unroll
    for (int nb = 0; nb < 2; ++nb) {
        int j = j0 + wN * 4 + nb * 2 + jA;
        bI[nb] = bv[j];
        bF[nb] = bv[HID + j];
        bG[nb] = bv[2 * HID + j];
        bO[nb] = bv[3 * HID + j];
    }
    float cst[4] = {0.f, 0.f, 0.f, 0.f};   // (rA,nb0),(rA+8,nb0),(rA,nb1),(rA+8,nb1)

    // A-loader coords: x region (rows 64 x 128 halfs), h region (64 x 256)
    const int xrow = tid >> 2, xkb = (tid & 3) * 32;     // x: 32 halfs/thread
    const int hkb  = (tid & 3) * 64;                     // h: 64 halfs/thread

    // ldmatrix per-thread addr bases (two m16 tiles)
    const int lrow = lane & 15, lkh = lane >> 4;
    uint32_t lds0 = sA_u + a_phys(0, wM * 32 + lrow, lkh);
    uint32_t lds1 = sA_u + a_phys(0, wM * 32 + 16 + lrow, lkh);

    // ---- prologue: stage x(0) into smem ----
    {
        const float* xp = x + ((size_t)(r0 + xrow) * SEQ + 0) * DIM + xkb;
        #pragma unroll
        for (int c2 = 0; c2 < 4; ++c2) {
            float4 v0 = *(const float4*)(xp + c2 * 8);
            float4 v1 = *(const float4*)(xp + c2 * 8 + 4);
            union { __half2 h; uint32_t u; } q0, q1, q2, q3;
            q0.h = __floats2half2_rn(v0.x, v0.y);
            q1.h = __floats2half2_rn(v0.z, v0.w);
            q2.h = __floats2half2_rn(v1.x, v1.y);
            q3.h = __floats2half2_rn(v1.z, v1.w);
            int k = xkb + c2 * 8;
            *(uint4*)(sA + a_phys(k >> 4, xrow, (k >> 3) & 1)) =
                make_uint4(q0.u, q1.u, q2.u, q3.u);
        }
    }

    grid_barrier();   // h0 zero + x(0) staged

    for (int s = 0; s < SEQ; ++s) {
        // -- load h(s) (L1-bypass: written by other SMs) and stage into smem
        const __half* hp = g_h16[s & 1];
        {
            const uint4* hsrc = (const uint4*)(hp + (size_t)(r0 + xrow) * HID + hkb);
            #pragma unroll
            for (int c = 0; c < 8; ++c) {
                uint4 hv = __ldcv(hsrc + c);
                int kg = DIM + hkb + c * 8;
                *(uint4*)(sA + a_phys(kg >> 4, xrow, (kg >> 3) & 1)) = hv;
            }
        }
        __syncthreads();

        // -- 24 k-steps of HMMA
        float acc[2][2][4];
        #pragma unroll
        for (int mb = 0; mb < 2; ++mb)
            #pragma unroll
            for (int nb = 0; nb < 2; ++nb)
                #pragma unroll
                for (int k = 0; k < 4; ++k) acc[mb][nb][k] = 0.f;

        #pragma unroll
        for (int ks = 0; ks < NKS; ++ks) {
            uint32_t am0[4], am1[4];
            ldsm4(am0, lds0 + ks * 2048);
            ldsm4(am1, lds1 + ks * 2048);
            mma16816(acc[0][0], am0, bfr[ks][0][0], bfr[ks][0][1]);
            mma16816(acc[0][1], am0, bfr[ks][1][0], bfr[ks][1][1]);
            mma16816(acc[1][0], am1, bfr[ks][0][0], bfr[ks][0][1]);
            mma16816(acc[1][1], am1, bfr[ks][1][0], bfr[ks][1][1]);
        }

        // -- pairwise gate exchange: even lanes own (i,f), odd own (g,o)
        float zif[2][4], zgo[2][4];
        #pragma unroll
        for (int nb = 0; nb < 2; ++nb)
            #pragma unroll
            for (int k = 0; k < 4; ++k) {
                float s0 = __shfl_xor_sync(0xffffffffu, acc[0][nb][k], 1);
                float s1 = __shfl_xor_sync(0xffffffffu, acc[1][nb][k], 1);
                zif[nb][k] = myOdd ? s1 : acc[0][nb][k];
                zgo[nb][k] = myOdd ? acc[1][nb][k] : s0;
            }

        // -- cell update + h store (fp16)
        __half* hn = g_h16[(s + 1) & 1];
        #pragma unroll
        for (int nb = 0; nb < 2; ++nb) {
            int j = j0 + wN * 4 + nb * 2 + jA;
            float i0 = sigf(zif[nb][0] + bI[nb]);
            float f0 = sigf(zif[nb][1] + bF[nb]);
            float g0 = tanhf_fast(zgo[nb][0] + bG[nb]);
            float o0 = sigf(zgo[nb][1] + bO[nb]);
            float i1 = sigf(zif[nb][2] + bI[nb]);
            float f1 = sigf(zif[nb][3] + bF[nb]);
            float g1 = tanhf_fast(zgo[nb][2] + bG[nb]);
            float o1 = sigf(zgo[nb][3] + bO[nb]);
            cst[nb * 2 + 0] = f0 * cst[nb * 2 + 0] + i0 * g0;
            cst[nb * 2 + 1] = f1 * cst[nb * 2 + 1] + i1 * g1;
            hn[(size_t)(r0 + rA) * HID + j] =
                __float2half_rn(o0 * tanhf_fast(cst[nb * 2 + 0]));
            hn[(size_t)(r0 + rA + 8) * HID + j] =
                __float2half_rn(o1 * tanhf_fast(cst[nb * 2 + 1]));
        }

        // -- stage x(s+1) before the barrier (hides DRAM under barrier skew)
        __syncthreads();                      // all warps done reading sA
        if (s + 1 < SEQ) {
            const float* xp = x + ((size_t)(r0 + xrow) * SEQ + (s + 1)) * DIM + xkb;
            #pragma unroll
            for (int c2 = 0; c2 < 4; ++c2) {
                float4 v0 = *(const float4*)(xp + c2 * 8);
                float4 v1 = *(const float4*)(xp + c2 * 8 + 4);
                union { __half2 h; uint32_t u; } q0, q1, q2, q3;
                q0.h = __floats2half2_rn(v0.x, v0.y);
                q1.h = __floats2half2_rn(v0.z, v0.w);
                q2.h = __floats2half2_rn(v1.x, v1.y);
                q3.h = __floats2half2_rn(v1.z, v1.w);
                int k = xkb + c2 * 8;
                *(uint4*)(sA + a_phys(k >> 4, xrow, (k >> 3) & 1)) =
                    make_uint4(q0.u, q1.u, q2.u, q3.u);
            }
        }

        grid_barrier();
    }

    // ---- classifier + softmax: 128 CTAs x 4 warps = 512 rows ----
    if (warp < 4) {
        const int row = cta * 4 + warp;
        const __half* hf = g_h16[0];
        float acc10[10];
        #pragma unroll
        for (int c = 0; c < 10; ++c) acc10[c] = 0.f;
        uint4 hv = __ldcv((const uint4*)(hf + (size_t)row * HID + lane * 8));
        const __half* hvh = (const __half*)&hv;
        #pragma unroll
        for (int u = 0; u < 8; ++u) {
            float h = __half2float(hvh[u]);
            const float* wd = Wd + (size_t)(lane * 8 + u) * 10;
            #pragma unroll
            for (int c = 0; c < 10; ++c) acc10[c] += h * wd[c];
        }
        #pragma unroll
        for (int off = 16; off > 0; off >>= 1) {
            #pragma unroll
            for (int c = 0; c < 10; ++c)
                acc10[c] += __shfl_down_sync(0xffffffffu, acc10[c], off);
        }
        if (lane == 0) {
            float m = -3.0e38f;
            #pragma unroll
            for (int c = 0; c < 10; ++c) { acc10[c] += bd[c]; m = fmaxf(m, acc10[c]); }
            float ssum = 0.f;
            #pragma unroll
            for (int c = 0; c < 10; ++c) { acc10[c] = __expf(acc10[c] - m); ssum += acc10[c]; }
            float inv = 1.0f / ssum;
            #pragma unroll
            for (int c = 0; c < 10; ++c) out[(size_t)row * 10 + c] = acc10[c] * inv;
        }
    }
}

extern "C" void kernel_launch(void* const* d_in, const int* in_sizes, int n_in,
                              void* d_out, int out_size) {
    const float* x  = (const float*)d_in[0];
    const float* Wx = (const float*)d_in[1];
    const float* Wh = (const float*)d_in[2];
    const float* b  = (const float*)d_in[3];
    const float* Wd = (const float*)d_in[4];
    const float* bd = (const float*)d_in[5];
    (void)in_sizes; (void)n_in; (void)out_size;
    lstm_hmma<<<NCTA, NTHR>>>(x, Wx, Wh, b, Wd, bd, (float*)d_out);
}